// round 1
// baseline (speedup 1.0000x reference)
#include <cuda_runtime.h>
#include <cuda_bf16.h>

// Problem constants (B=1, C=2, T=64, V=2, NX=512, NY=512, DX=0.1)
#define T_DIM      64
#define NY_DIM     512
#define NXY        (512 * 512)          // elements per (t, v) plane
#define CH_PER_T   (NXY / 4)            // 65536 float4 chunks per plane per t
#define BLKS_PER_T 64
#define NTHREADS   256
#define CH_PER_BLK (CH_PER_T / BLKS_PER_T)   // 1024
#define NITERS     (CH_PER_BLK / NTHREADS)   // 4

// Scratch: fully overwritten by every launch of reduce_kernel -> deterministic,
// no zero-init needed, graph-replay safe.
__device__ float g_partial[T_DIM * BLKS_PER_T];

__global__ __launch_bounds__(NTHREADS)
void reduce_kernel(const float* __restrict__ x) {
    const int t   = blockIdx.x / BLKS_PER_T;
    const int blk = blockIdx.x % BLKS_PER_T;

    // x layout: [b][c][t][v][ix][iy]; we need c=0 only.
    // n  = x[0,0,t,0,:,:]  (contiguous NXY floats)
    // phi= x[0,0,t,1,:,:]  (contiguous NXY floats, right after n)
    const float*  nptr = x + (size_t)t * (2u * NXY);
    const float*  pptr = nptr + NXY;
    const float4* n4   = reinterpret_cast<const float4*>(nptr);
    const float4* p4   = reinterpret_cast<const float4*>(pptr);

    const float inv2 = 0.5f / 0.1f;   // 5.0  (central)
    const float inv1 = 1.0f / 0.1f;   // 10.0 (one-sided)

    float acc = 0.0f;
    const int base = blk * CH_PER_BLK + threadIdx.x;

#pragma unroll
    for (int j = 0; j < NITERS; ++j) {
        const int c = base + j * NTHREADS;          // float4 chunk index in plane
        const float4 nv = __ldg(n4 + c);
        const float4 pv = __ldg(p4 + c);

        const int r = c & (NY_DIM / 4 - 1);         // chunk index within its row (0..127)
        // Stencil halo (L1 hits: same cache lines as neighbor chunks)
        const float pm1 = (r != 0)   ? __ldg(pptr + 4 * (size_t)c - 1) : 0.0f;
        const float pp4 = (r != 127) ? __ldg(pptr + 4 * (size_t)c + 4) : 0.0f;

        const float g0 = (r == 0)   ? (pv.y - pv.x) * inv1 : (pv.y - pm1)  * inv2;
        const float g1 =                                     (pv.z - pv.x) * inv2;
        const float g2 =                                     (pv.w - pv.y) * inv2;
        const float g3 = (r == 127) ? (pv.w - pv.z) * inv1 : (pp4  - pv.z) * inv2;

        acc += nv.x * g0 + nv.y * g1 + nv.z * g2 + nv.w * g3;
    }

    // Deterministic block reduction
    __shared__ float sm[NTHREADS / 32];
#pragma unroll
    for (int o = 16; o > 0; o >>= 1)
        acc += __shfl_down_sync(0xffffffffu, acc, o);
    if ((threadIdx.x & 31) == 0) sm[threadIdx.x >> 5] = acc;
    __syncthreads();
    if (threadIdx.x < (NTHREADS / 32)) {
        float v = sm[threadIdx.x];
#pragma unroll
        for (int o = (NTHREADS / 64); o > 0; o >>= 1)
            v += __shfl_down_sync(0xffu, v, o);
        if (threadIdx.x == 0) g_partial[blockIdx.x] = v;
    }
}

__global__ void mlp_kernel(const float* __restrict__ idrv,
                           const float* __restrict__ w1,
                           const float* __restrict__ b1,
                           const float* __restrict__ w2,
                           const float* __restrict__ b2,
                           float* __restrict__ out) {
    const int t = threadIdx.x;
    if (t >= T_DIM) return;

    float s = 0.0f;
#pragma unroll
    for (int i = 0; i < BLKS_PER_T; ++i)
        s += g_partial[t * BLKS_PER_T + i];

    const float gamma = -s * (1.0f / (float)NXY);
    const float f0 = idrv[t];
    const float f1 = gamma;

    float o = b2[0];
#pragma unroll
    for (int h = 0; h < 4; ++h) {
        const float pre = w1[2 * h] * f0 + w1[2 * h + 1] * f1 + b1[h];
        // JAX default gelu (approximate=True, tanh form)
        const float g = 0.5f * pre *
            (1.0f + tanhf(0.7978845608028654f * (pre + 0.044715f * pre * pre * pre)));
        o += w2[h] * g;
    }
    out[t] = o;
}

extern "C" void kernel_launch(void* const* d_in, const int* in_sizes, int n_in,
                              void* d_out, int out_size) {
    const float* x    = (const float*)d_in[0];  // (1,2,64,2,512,512) f32
    const float* idrv = (const float*)d_in[1];  // (1,64)  f32
    const float* w1   = (const float*)d_in[2];  // (4,2)   f32
    const float* b1   = (const float*)d_in[3];  // (4,)    f32
    const float* w2   = (const float*)d_in[4];  // (1,4)   f32
    const float* b2   = (const float*)d_in[5];  // (1,)    f32
    float* out        = (float*)d_out;          // 64 f32

    reduce_kernel<<<T_DIM * BLKS_PER_T, NTHREADS>>>(x);
    mlp_kernel<<<1, 64>>>(idrv, w1, b1, w2, b2, out);
}